// round 14
// baseline (speedup 1.0000x reference)
#include <cuda_runtime.h>
#include <cuda_bf16.h>
#include <cuda_fp16.h>
#include <math.h>
#include <stdint.h>

#define D 128
#define NMAX 100000
#define EMAX 1600000
#define NSB 592            // spmm blocks == colstats partials
#define SCAN_ELEMS 4096    // per scan block (1024 thr x 4)
#define LMAX 4
#define ASTRIDE 68         // u32 words per SMEM row (68 % 32 == 4 -> conflict-free frags)

// ---------------- device scratch (static; no runtime allocation) ----------------
__device__ int   g_cnt[NMAX + 4];
__device__ int   g_rowptr[NMAX + 1];
__device__ int   g_cursor[NMAX + 4];
__device__ int   g_colidx[EMAX];
__device__ float g_dinv[NMAX + 4];
__device__ __align__(16) __half g_tt_h[(size_t)NMAX * D];  // fp16 dinv*(h@W)
__device__ float g_agg[(size_t)NMAX * D];  // aggregated (pre-BN) features
__device__ float g_psum[NSB * D];
__device__ float g_psq[NSB * D];
__device__ float g_scale[D];               // BN folded: h = relu(scale*agg + shift)
__device__ float g_shift[D];
__device__ int   g_blksum[64];
__device__ unsigned int g_ctr = 0;         // spmm last-block counter (wraps to 0)
// W^T split into bf16 hi/lo: [layer][n*128 + k] (n-major, k contiguous)
__device__ __align__(16) __nv_bfloat16 g_wt_hi[LMAX][16384];
__device__ __align__(16) __nv_bfloat16 g_wt_lo[LMAX][16384];

// ---------------- fused prep: zero cnt + W split + BN identity ----------------
__global__ void prep_kernel(const float* __restrict__ Ws, int L, int n) {
    int idx = blockIdx.x * blockDim.x + threadIdx.x;
    if (idx < n) g_cnt[idx] = 0;
    if (idx < 128) { g_scale[idx] = 1.0f; g_shift[idx] = 0.0f; }
    if (idx < L * 16384) {
        int l = idx >> 14;
        int e = idx & 16383;
        int nn = e >> 7;    // output col (B "row" in n-major layout)
        int kk = e & 127;   // K
        float w = Ws[(size_t)l * 16384 + kk * 128 + nn];   // W[k][n]
        __nv_bfloat16 hi = __float2bfloat16(w);
        __nv_bfloat16 lo = __float2bfloat16(w - __bfloat162float(hi));
        g_wt_hi[l][nn * 128 + kk] = hi;
        g_wt_lo[l][nn * 128 + kk] = lo;
    }
}

__global__ void count_kernel(const int* __restrict__ dst, int E) {
    int e = blockIdx.x * blockDim.x + threadIdx.x;
    if (e < E) atomicAdd(&g_cnt[dst[e]], 1);
}

__global__ __launch_bounds__(1024)
void scan_reduce_kernel(int n) {
    int base = blockIdx.x * SCAN_ELEMS + threadIdx.x * 4;
    int s = 0;
    if (base + 3 < n) {
        int4 v = *(const int4*)(g_cnt + base);
        s = (v.x + v.y) + (v.z + v.w);
    } else {
        for (int k = 0; k < 4; k++) if (base + k < n) s += g_cnt[base + k];
    }
#pragma unroll
    for (int off = 16; off > 0; off >>= 1)
        s += __shfl_down_sync(0xffffffffu, s, off);
    __shared__ int ws[32];
    int lane = threadIdx.x & 31, warp = threadIdx.x >> 5;
    if (lane == 0) ws[warp] = s;
    __syncthreads();
    if (warp == 0) {
        s = ws[lane];
#pragma unroll
        for (int off = 16; off > 0; off >>= 1)
            s += __shfl_down_sync(0xffffffffu, s, off);
        if (lane == 0) g_blksum[blockIdx.x] = s;
    }
}

// writes rowptr/cursor/dinv; each block re-derives its own blkoff from g_blksum
__global__ __launch_bounds__(1024)
void scan_write_kernel(int n, int nblk) {
    __shared__ int s_blkoff;
    // warp 0: scan the <=25 block sums
    if (threadIdx.x < 32) {
        int v = ((int)threadIdx.x < nblk) ? g_blksum[threadIdx.x] : 0;
        int inc = v;
#pragma unroll
        for (int off = 1; off < 32; off <<= 1) {
            int u = __shfl_up_sync(0xffffffffu, inc, off);
            if ((int)threadIdx.x >= off) inc += u;
        }
        if ((int)threadIdx.x == (int)blockIdx.x) s_blkoff = inc - v;
        if (blockIdx.x == 0 && threadIdx.x == 31) g_rowptr[n] = inc;
    }
    __syncthreads();

    int base = blockIdx.x * SCAN_ELEMS + threadIdx.x * 4;
    int c0 = 0, c1 = 0, c2 = 0, c3 = 0;
    bool full = (base + 3 < n);
    if (full) {
        int4 v = *(const int4*)(g_cnt + base);
        c0 = v.x; c1 = v.y; c2 = v.z; c3 = v.w;
    } else {
        if (base + 0 < n) c0 = g_cnt[base + 0];
        if (base + 1 < n) c1 = g_cnt[base + 1];
        if (base + 2 < n) c2 = g_cnt[base + 2];
        if (base + 3 < n) c3 = g_cnt[base + 3];
    }
    int tsum = (c0 + c1) + (c2 + c3);
    int lane = threadIdx.x & 31, warp = threadIdx.x >> 5;
    int inc = tsum;
#pragma unroll
    for (int off = 1; off < 32; off <<= 1) {
        int u = __shfl_up_sync(0xffffffffu, inc, off);
        if (lane >= off) inc += u;
    }
    __shared__ int ws[32];
    if (lane == 31) ws[warp] = inc;
    __syncthreads();
    if (warp == 0) {
        int v = ws[lane];
        int i2 = v;
#pragma unroll
        for (int off = 1; off < 32; off <<= 1) {
            int u = __shfl_up_sync(0xffffffffu, i2, off);
            if (lane >= off) i2 += u;
        }
        ws[lane] = i2 - v;
    }
    __syncthreads();
    int p = s_blkoff + ws[warp] + (inc - tsum);
    int4 rp;
    rp.x = p; p += c0;
    rp.y = p; p += c1;
    rp.z = p; p += c2;
    rp.w = p;
    float4 dv;
    dv.x = rsqrtf((float)(c0 + 1));
    dv.y = rsqrtf((float)(c1 + 1));
    dv.z = rsqrtf((float)(c2 + 1));
    dv.w = rsqrtf((float)(c3 + 1));
    if (full) {
        *(int4*)(g_rowptr + base) = rp;
        *(int4*)(g_cursor + base) = rp;
        *(float4*)(g_dinv + base) = dv;
    } else {
        int rr[4] = {rp.x, rp.y, rp.z, rp.w};
        float dd[4] = {dv.x, dv.y, dv.z, dv.w};
        for (int k = 0; k < 4; k++)
            if (base + k < n) {
                g_rowptr[base + k] = rr[k];
                g_cursor[base + k] = rr[k];
                g_dinv[base + k] = dd[k];
            }
    }
}

__global__ void scatter_kernel(const int* __restrict__ src,
                               const int* __restrict__ dst, int E) {
    int e = blockIdx.x * blockDim.x + threadIdx.x;
    if (e < E) {
        int d = dst[e];
        int p = atomicAdd(&g_cursor[d], 1);
        g_colidx[p] = src[e];
    }
}

// ---------------- HMMA GEMM: g_tt_h = fp16( dinv ⊙ ( relu?(bn?(A)) @ W ) ) ----------------
// CTA tile 128x128, 8 warps (4M x 2N), warp tile m32 x n64, K=128.
// Split-bf16: A@W = Ah@Wh + Ah@Wl + Al@Wh, fp32 accumulators. (R7/R10 proven)
__device__ __forceinline__ void mma16816(float* d, const uint32_t* a,
                                         const uint32_t* b) {
    asm volatile(
        "mma.sync.aligned.m16n8k16.row.col.f32.bf16.bf16.f32 "
        "{%0,%1,%2,%3}, {%4,%5,%6,%7}, {%8,%9}, {%0,%1,%2,%3};"
        : "+f"(d[0]), "+f"(d[1]), "+f"(d[2]), "+f"(d[3])
        : "r"(a[0]), "r"(a[1]), "r"(a[2]), "r"(a[3]), "r"(b[0]), "r"(b[1]));
}

__device__ __forceinline__ uint32_t pack_bf16x2(float x, float y) {
    __nv_bfloat162 p;
    p.x = __float2bfloat16(x);
    p.y = __float2bfloat16(y);
    return *(uint32_t*)&p;
}

__global__ __launch_bounds__(256, 1)
void mma_gemm_kernel(const float* __restrict__ Ain, int layer, int n,
                     int applyBN) {
    extern __shared__ uint32_t smem[];
    uint32_t* sAh = smem;                       // 128 * ASTRIDE
    uint32_t* sAl = smem + 128 * ASTRIDE;
    uint32_t* sBh = smem + 2 * 128 * ASTRIDE;
    uint32_t* sBl = smem + 3 * 128 * ASTRIDE;
    int t = threadIdx.x;

    // ---- stage B: vectorized repack [n][k] -> smem stride ASTRIDE
    {
        const uint4* wh = (const uint4*)g_wt_hi[layer];
        const uint4* wl = (const uint4*)g_wt_lo[layer];
#pragma unroll
        for (int ii = 0; ii < 8; ii++) {
            int gidx = t + 256 * ii;       // uint4 index 0..2047
            int i = gidx * 4;              // word index
            int nn = i >> 6, q = i & 63;
            uint4 vh = wh[gidx];
            uint4 vl = wl[gidx];
            *(uint4*)&sBh[nn * ASTRIDE + q] = vh;
            *(uint4*)&sBl[nn * ASTRIDE + q] = vl;
        }
    }

    // ---- stage A: BN+ReLU then hi/lo bf16 split; 2 threads per row
    {
        const float* A = Ain ? Ain : g_agg;
        int r = t >> 1, half = t & 1;
        int grow = blockIdx.x * 128 + r;
        bool ok = (grow < n);
        const float* arow = A + (size_t)grow * 128 + half * 64;
        const float* scp = g_scale + half * 64;
        const float* shp = g_shift + half * 64;
        int wbase = r * ASTRIDE + half * 32;
#pragma unroll
        for (int i = 0; i < 16; i++) {
            float4 v = make_float4(0.f, 0.f, 0.f, 0.f);
            if (ok) v = *(const float4*)(arow + 4 * i);
            if (applyBN) {
                float4 sc = *(const float4*)(scp + 4 * i);
                float4 sh = *(const float4*)(shp + 4 * i);
                v.x = fmaxf(fmaf(v.x, sc.x, sh.x), 0.f);
                v.y = fmaxf(fmaf(v.y, sc.y, sh.y), 0.f);
                v.z = fmaxf(fmaf(v.z, sc.z, sh.z), 0.f);
                v.w = fmaxf(fmaf(v.w, sc.w, sh.w), 0.f);
            }
            uint2 hh, ll;
            hh.x = pack_bf16x2(v.x, v.y);
            hh.y = pack_bf16x2(v.z, v.w);
            float rx = v.x - __bfloat162float(__float2bfloat16(v.x));
            float ry = v.y - __bfloat162float(__float2bfloat16(v.y));
            float rz = v.z - __bfloat162float(__float2bfloat16(v.z));
            float rw = v.w - __bfloat162float(__float2bfloat16(v.w));
            ll.x = pack_bf16x2(rx, ry);
            ll.y = pack_bf16x2(rz, rw);
            *(uint2*)&sAh[wbase + 2 * i] = hh;
            *(uint2*)&sAl[wbase + 2 * i] = ll;
        }
    }
    __syncthreads();

    // ---- mainloop (pass-wise: proven fastest)
    int warp = t >> 5, lane = t & 31;
    int wm = (warp & 3) * 32;
    int wn = (warp >> 2) * 64;
    int qr = lane >> 2, qc = lane & 3;

    float acc[2][8][4];
#pragma unroll
    for (int mt = 0; mt < 2; mt++)
#pragma unroll
        for (int nt = 0; nt < 8; nt++)
#pragma unroll
            for (int j = 0; j < 4; j++) acc[mt][nt][j] = 0.f;

    const uint32_t* Aps[3] = { sAh, sAh, sAl };
    const uint32_t* Bps[3] = { sBh, sBl, sBh };

#pragma unroll
    for (int p = 0; p < 3; p++) {
        const uint32_t* a = Aps[p];
        const uint32_t* b = Bps[p];
#pragma unroll
        for (int ks = 0; ks < 8; ks++) {
            uint32_t af[2][4];
#pragma unroll
            for (int mt = 0; mt < 2; mt++) {
                int base = (wm + mt * 16 + qr) * ASTRIDE + ks * 8 + qc;
                af[mt][0] = a[base];
                af[mt][1] = a[base + 8 * ASTRIDE];
                af[mt][2] = a[base + 4];
                af[mt][3] = a[base + 8 * ASTRIDE + 4];
            }
            uint32_t bf[8][2];
#pragma unroll
            for (int nt = 0; nt < 8; nt++) {
                int nb = (wn + nt * 8 + qr) * ASTRIDE + ks * 8 + qc;
                bf[nt][0] = b[nb];
                bf[nt][1] = b[nb + 4];
            }
#pragma unroll
            for (int mt = 0; mt < 2; mt++)
#pragma unroll
                for (int nt = 0; nt < 8; nt++)
                    mma16816(acc[mt][nt], af[mt], bf[nt]);
        }
    }

    // ---- epilogue: scale by dinv[row], convert fp16, store to g_tt_h
#pragma unroll
    for (int mt = 0; mt < 2; mt++) {
        int r0 = blockIdx.x * 128 + wm + mt * 16 + qr;
        int r1 = r0 + 8;
        bool ok0 = (r0 < n), ok1 = (r1 < n);
        float dv0 = ok0 ? g_dinv[r0] : 0.f;
        float dv1 = ok1 ? g_dinv[r1] : 0.f;
        __half* p0 = g_tt_h + (size_t)r0 * 128 + wn + qc * 2;
        __half* p1 = g_tt_h + (size_t)r1 * 128 + wn + qc * 2;
#pragma unroll
        for (int nt = 0; nt < 8; nt++) {
            if (ok0)
                *(__half2*)(p0 + nt * 8) =
                    __floats2half2_rn(acc[mt][nt][0] * dv0, acc[mt][nt][1] * dv0);
            if (ok1)
                *(__half2*)(p1 + nt * 8) =
                    __floats2half2_rn(acc[mt][nt][2] * dv1, acc[mt][nt][3] * dv1);
        }
    }
}

// ---------------- SpMM gather (fp16 rows, fp32 accum, MLP=8) + fused stats
// ---------------- + last-block BN finalize (replaces bnfinal kernel) -----------
__device__ __forceinline__ void acc_u2(float4& a, uint2 u) {
    float2 f0 = __half22float2(*(__half2*)&u.x);
    float2 f1 = __half22float2(*(__half2*)&u.y);
    a.x += f0.x; a.y += f0.y; a.z += f1.x; a.w += f1.y;
}

__global__ __launch_bounds__(256)
void spmm_kernel(const float* __restrict__ bias,
                 const float* __restrict__ gamma,
                 const float* __restrict__ beta,
                 float* __restrict__ pool, int G, int zeroPool, int n) {
    __shared__ float s_ps[8][128];
    __shared__ float s_pq[8][128];
    int warp = threadIdx.x >> 5;
    int lane = threadIdx.x & 31;
    int gw = (blockIdx.x << 3) + warp;
    int nwarps = gridDim.x << 3;
    int c = lane * 4;
    float4 b4 = *(const float4*)(bias + c);

    float4 ps = make_float4(0.f, 0.f, 0.f, 0.f);
    float4 pq = make_float4(0.f, 0.f, 0.f, 0.f);

    for (int i = gw; i < n; i += nwarps) {
        int s = g_rowptr[i], e = g_rowptr[i + 1];
        float4 acc = make_float4(0.f, 0.f, 0.f, 0.f);
        float4 acc2 = make_float4(0.f, 0.f, 0.f, 0.f);
        {   // self loop
            uint2 u = *(const uint2*)(g_tt_h + (size_t)i * D + c);
            acc_u2(acc, u);
        }
        for (int base = s; base < e; base += 32) {
            int rem = e - base;
            int m = rem < 32 ? rem : 32;
            int idx = 0;
            if (base + lane < e) idx = g_colidx[base + lane];
            int j = 0;
            for (; j + 8 <= m; j += 8) {
                int s0 = __shfl_sync(0xffffffffu, idx, j);
                int s1 = __shfl_sync(0xffffffffu, idx, j + 1);
                int s2 = __shfl_sync(0xffffffffu, idx, j + 2);
                int s3 = __shfl_sync(0xffffffffu, idx, j + 3);
                int s4 = __shfl_sync(0xffffffffu, idx, j + 4);
                int s5 = __shfl_sync(0xffffffffu, idx, j + 5);
                int s6 = __shfl_sync(0xffffffffu, idx, j + 6);
                int s7 = __shfl_sync(0xffffffffu, idx, j + 7);
                uint2 u0 = *(const uint2*)(g_tt_h + (size_t)s0 * D + c);
                uint2 u1 = *(const uint2*)(g_tt_h + (size_t)s1 * D + c);
                uint2 u2 = *(const uint2*)(g_tt_h + (size_t)s2 * D + c);
                uint2 u3 = *(const uint2*)(g_tt_h + (size_t)s3 * D + c);
                uint2 u4 = *(const uint2*)(g_tt_h + (size_t)s4 * D + c);
                uint2 u5 = *(const uint2*)(g_tt_h + (size_t)s5 * D + c);
                uint2 u6 = *(const uint2*)(g_tt_h + (size_t)s6 * D + c);
                uint2 u7 = *(const uint2*)(g_tt_h + (size_t)s7 * D + c);
                acc_u2(acc, u0);  acc_u2(acc2, u1);
                acc_u2(acc, u2);  acc_u2(acc2, u3);
                acc_u2(acc, u4);  acc_u2(acc2, u5);
                acc_u2(acc, u6);  acc_u2(acc2, u7);
            }
            for (; j + 4 <= m; j += 4) {
                int s0 = __shfl_sync(0xffffffffu, idx, j);
                int s1 = __shfl_sync(0xffffffffu, idx, j + 1);
                int s2 = __shfl_sync(0xffffffffu, idx, j + 2);
                int s3 = __shfl_sync(0xffffffffu, idx, j + 3);
                uint2 u0 = *(const uint2*)(g_tt_h + (size_t)s0 * D + c);
                uint2 u1 = *(const uint2*)(g_tt_h + (size_t)s1 * D + c);
                uint2 u2 = *(const uint2*)(g_tt_h + (size_t)s2 * D + c);
                uint2 u3 = *(const uint2*)(g_tt_h + (size_t)s3 * D + c);
                acc_u2(acc, u0);  acc_u2(acc2, u1);
                acc_u2(acc, u2);  acc_u2(acc2, u3);
            }
            for (; j < m; j++) {
                int s0 = __shfl_sync(0xffffffffu, idx, j);
                uint2 u = *(const uint2*)(g_tt_h + (size_t)s0 * D + c);
                acc_u2(acc, u);
            }
        }
        acc.x += acc2.x; acc.y += acc2.y; acc.z += acc2.z; acc.w += acc2.w;
        float dv = g_dinv[i];
        float4 o;
        o.x = fmaf(acc.x, dv, b4.x);
        o.y = fmaf(acc.y, dv, b4.y);
        o.z = fmaf(acc.z, dv, b4.z);
        o.w = fmaf(acc.w, dv, b4.w);
        *(float4*)(g_agg + (size_t)i * D + c) = o;
        ps.x += o.x; ps.y += o.y; ps.z += o.z; ps.w += o.w;
        pq.x = fmaf(o.x, o.x, pq.x);
        pq.y = fmaf(o.y, o.y, pq.y);
        pq.z = fmaf(o.z, o.z, pq.z);
        pq.w = fmaf(o.w, o.w, pq.w);
    }

    *(float4*)&s_ps[warp][c] = ps;
    *(float4*)&s_pq[warp][c] = pq;
    __syncthreads();

    int t = threadIdx.x;
    int col = t & 127;
    bool doSq = (t >= 128);
    {
        float a = 0.f;
#pragma unroll
        for (int w = 0; w < 8; w++)
            a += doSq ? s_pq[w][col] : s_ps[w][col];
        if (doSq) g_psq[blockIdx.x * D + col] = a;
        else      g_psum[blockIdx.x * D + col] = a;
    }

    // ---- last-block BN finalize (deterministic: counter wraps to 0 per launch)
    __shared__ int s_last;
    __threadfence();
    __syncthreads();
    if (t == 0)
        s_last = (atomicInc(&g_ctr, NSB - 1) == NSB - 1) ? 1 : 0;
    __syncthreads();
    if (s_last) {
        float a = 0.f;
        const float* src = doSq ? g_psq : g_psum;
#pragma unroll 8
        for (int b = 0; b < NSB; b++)
            a += src[b * D + col];
        __shared__ float s_sum[128], s_sq[128];
        if (doSq) s_sq[col] = a; else s_sum[col] = a;
        __syncthreads();
        if (t < 128) {
            float inv_n = 1.0f / (float)n;
            float mu = s_sum[t] * inv_n;
            float var = fmaxf(s_sq[t] * inv_n - mu * mu, 0.f);
            float rsq = rsqrtf(var + 1e-5f);
            float sc = gamma[t] * rsq;
            g_scale[t] = sc;
            g_shift[t] = fmaf(-mu, sc, beta[t]);
        }
        if (zeroPool) {
            for (int g = t; g < G * D; g += 256)
                pool[g] = 0.f;
        }
    }
}

// ---------------- final BN+ReLU -> h out, pooled sum -> pool out ----------------
__global__ void finalize_kernel(const int* __restrict__ batch,
                                float* __restrict__ hout,
                                float* __restrict__ pool, int n) {
    int gw = (blockIdx.x * blockDim.x + threadIdx.x) >> 5;
    int lane = threadIdx.x & 31;
    int nch = (n + 15) >> 4;
    if (gw >= nch) return;
    int r0 = gw << 4;
    int r1 = r0 + 16; if (r1 > n) r1 = n;
    int c = lane * 4;
    float4 sc = *(const float4*)(g_scale + c);
    float4 sh = *(const float4*)(g_shift + c);

    float4 acc = make_float4(0.f, 0.f, 0.f, 0.f);
    int gprev = -1;
    for (int r = r0; r < r1; r++) {
        float4 v = *(const float4*)(g_agg + (size_t)r * D + c);
        float4 h;
        h.x = fmaxf(fmaf(v.x, sc.x, sh.x), 0.f);
        h.y = fmaxf(fmaf(v.y, sc.y, sh.y), 0.f);
        h.z = fmaxf(fmaf(v.z, sc.z, sh.z), 0.f);
        h.w = fmaxf(fmaf(v.w, sc.w, sh.w), 0.f);
        *(float4*)(hout + (size_t)r * D + c) = h;
        int g = batch[r];
        if (g != gprev) {
            if (gprev >= 0) {
                float* p = pool + (size_t)gprev * D + c;
                atomicAdd(p + 0, acc.x); atomicAdd(p + 1, acc.y);
                atomicAdd(p + 2, acc.z); atomicAdd(p + 3, acc.w);
            }
            acc = make_float4(0.f, 0.f, 0.f, 0.f);
            gprev = g;
        }
        acc.x += h.x; acc.y += h.y; acc.z += h.z; acc.w += h.w;
    }
    if (gprev >= 0) {
        float* p = pool + (size_t)gprev * D + c;
        atomicAdd(p + 0, acc.x); atomicAdd(p + 1, acc.y);
        atomicAdd(p + 2, acc.z); atomicAdd(p + 3, acc.w);
    }
}

// ---------------- launch ----------------
extern "C" void kernel_launch(void* const* d_in, const int* in_sizes, int n_in,
                              void* d_out, int out_size) {
    const float* x      = (const float*)d_in[0];
    const int*   ei     = (const int*)d_in[1];
    const int*   batch  = (const int*)d_in[2];
    const float* Ws     = (const float*)d_in[3];
    const float* bs     = (const float*)d_in[4];
    const float* gammas = (const float*)d_in[5];
    const float* betas  = (const float*)d_in[6];

    int n = in_sizes[2];
    int E = in_sizes[1] / 2;
    int L = in_sizes[3] / (D * D);
    int G = out_size / D - n;

    const int* src = ei;
    const int* dst = ei + E;
    float* hout = (float*)d_out;
    float* pool = hout + (size_t)n * D;

    const int tb = 256;
    int nblk = (n + SCAN_ELEMS - 1) / SCAN_ELEMS;

    const int DYN_SMEM = 4 * 128 * ASTRIDE * 4;   // 139264 bytes
    cudaFuncSetAttribute(mma_gemm_kernel,
                         cudaFuncAttributeMaxDynamicSharedMemorySize, DYN_SMEM);

    // Graph preprocessing (5 launches)
    int prepN = n > L * 16384 ? n : L * 16384;
    prep_kernel<<<(prepN + tb - 1) / tb, tb>>>(Ws, L, n);
    count_kernel<<<(E + tb - 1) / tb, tb>>>(dst, E);
    scan_reduce_kernel<<<nblk, 1024>>>(n);
    scan_write_kernel<<<nblk, 1024>>>(n, nblk);
    scatter_kernel<<<(E + tb - 1) / tb, tb>>>(src, dst, E);

    int gblocks = (n + 127) / 128;
    for (int l = 0; l < L; l++) {
        mma_gemm_kernel<<<gblocks, 256, DYN_SMEM>>>(l == 0 ? x : nullptr,
                                                    l, n, l > 0 ? 1 : 0);
        spmm_kernel<<<NSB, 256>>>(bs + (size_t)l * D,
                                  gammas + (size_t)l * D,
                                  betas + (size_t)l * D,
                                  pool, G, (l == L - 1) ? 1 : 0, n);
    }

    int nch = (n + 15) / 16;
    finalize_kernel<<<(nch * 32 + tb - 1) / tb, tb>>>(batch, hout, pool, n);
}

// round 16
// speedup vs baseline: 1.1319x; 1.1319x over previous
#include <cuda_runtime.h>
#include <cuda_bf16.h>
#include <cuda_fp16.h>
#include <math.h>
#include <stdint.h>

#define D 128
#define NMAX 100000
#define EMAX 1600000
#define NSB 592            // spmm blocks == colstats partials
#define SCAN_ELEMS 4096    // per scan block (1024 thr x 4)
#define LMAX 4
#define ASTRIDE 68         // u32 words per SMEM row (68 % 32 == 4 -> conflict-free frags)

// ---------------- device scratch (static; no runtime allocation) ----------------
__device__ int   g_cnt[NMAX + 4];
__device__ int   g_rowptr[NMAX + 1];
__device__ int   g_cursor[NMAX + 4];
__device__ int   g_colidx[EMAX];
__device__ float g_dinv[NMAX + 4];
__device__ __align__(16) __half g_tt_h[(size_t)NMAX * D];  // fp16 dinv*(h@W)
__device__ float g_agg[(size_t)NMAX * D];  // aggregated (pre-BN) features
__device__ float g_psum[NSB * D];
__device__ float g_psq[NSB * D];
__device__ float g_scale[D];               // BN folded: h = relu(scale*agg + shift)
__device__ float g_shift[D];
__device__ int   g_blksum[64];
// W^T split into bf16 hi/lo: [layer][n*128 + k] (n-major, k contiguous)
__device__ __align__(16) __nv_bfloat16 g_wt_hi[LMAX][16384];
__device__ __align__(16) __nv_bfloat16 g_wt_lo[LMAX][16384];

// ---------------- fused prep: zero cnt + W split + BN identity ----------------
__global__ void prep_kernel(const float* __restrict__ Ws, int L, int n) {
    int idx = blockIdx.x * blockDim.x + threadIdx.x;
    if (idx < n) g_cnt[idx] = 0;
    if (idx < 128) { g_scale[idx] = 1.0f; g_shift[idx] = 0.0f; }
    if (idx < L * 16384) {
        int l = idx >> 14;
        int e = idx & 16383;
        int nn = e >> 7;    // output col (B "row" in n-major layout)
        int kk = e & 127;   // K
        float w = Ws[(size_t)l * 16384 + kk * 128 + nn];   // W[k][n]
        __nv_bfloat16 hi = __float2bfloat16(w);
        __nv_bfloat16 lo = __float2bfloat16(w - __bfloat162float(hi));
        g_wt_hi[l][nn * 128 + kk] = hi;
        g_wt_lo[l][nn * 128 + kk] = lo;
    }
}

__global__ void count_kernel(const int* __restrict__ dst, int E) {
    int e = blockIdx.x * blockDim.x + threadIdx.x;
    if (e < E) atomicAdd(&g_cnt[dst[e]], 1);
}

__global__ __launch_bounds__(1024)
void scan_reduce_kernel(int n) {
    int base = blockIdx.x * SCAN_ELEMS + threadIdx.x * 4;
    int s = 0;
    if (base + 3 < n) {
        int4 v = *(const int4*)(g_cnt + base);
        s = (v.x + v.y) + (v.z + v.w);
    } else {
        for (int k = 0; k < 4; k++) if (base + k < n) s += g_cnt[base + k];
    }
#pragma unroll
    for (int off = 16; off > 0; off >>= 1)
        s += __shfl_down_sync(0xffffffffu, s, off);
    __shared__ int ws[32];
    int lane = threadIdx.x & 31, warp = threadIdx.x >> 5;
    if (lane == 0) ws[warp] = s;
    __syncthreads();
    if (warp == 0) {
        s = ws[lane];
#pragma unroll
        for (int off = 16; off > 0; off >>= 1)
            s += __shfl_down_sync(0xffffffffu, s, off);
        if (lane == 0) g_blksum[blockIdx.x] = s;
    }
}

// writes rowptr/cursor/dinv; each block re-derives its own blkoff from g_blksum
__global__ __launch_bounds__(1024)
void scan_write_kernel(int n, int nblk) {
    __shared__ int s_blkoff;
    if (threadIdx.x < 32) {
        int v = ((int)threadIdx.x < nblk) ? g_blksum[threadIdx.x] : 0;
        int inc = v;
#pragma unroll
        for (int off = 1; off < 32; off <<= 1) {
            int u = __shfl_up_sync(0xffffffffu, inc, off);
            if ((int)threadIdx.x >= off) inc += u;
        }
        if ((int)threadIdx.x == (int)blockIdx.x) s_blkoff = inc - v;
        if (blockIdx.x == 0 && threadIdx.x == 31) g_rowptr[n] = inc;
    }
    __syncthreads();

    int base = blockIdx.x * SCAN_ELEMS + threadIdx.x * 4;
    int c0 = 0, c1 = 0, c2 = 0, c3 = 0;
    bool full = (base + 3 < n);
    if (full) {
        int4 v = *(const int4*)(g_cnt + base);
        c0 = v.x; c1 = v.y; c2 = v.z; c3 = v.w;
    } else {
        if (base + 0 < n) c0 = g_cnt[base + 0];
        if (base + 1 < n) c1 = g_cnt[base + 1];
        if (base + 2 < n) c2 = g_cnt[base + 2];
        if (base + 3 < n) c3 = g_cnt[base + 3];
    }
    int tsum = (c0 + c1) + (c2 + c3);
    int lane = threadIdx.x & 31, warp = threadIdx.x >> 5;
    int inc = tsum;
#pragma unroll
    for (int off = 1; off < 32; off <<= 1) {
        int u = __shfl_up_sync(0xffffffffu, inc, off);
        if (lane >= off) inc += u;
    }
    __shared__ int ws[32];
    if (lane == 31) ws[warp] = inc;
    __syncthreads();
    if (warp == 0) {
        int v = ws[lane];
        int i2 = v;
#pragma unroll
        for (int off = 1; off < 32; off <<= 1) {
            int u = __shfl_up_sync(0xffffffffu, i2, off);
            if (lane >= off) i2 += u;
        }
        ws[lane] = i2 - v;
    }
    __syncthreads();
    int p = s_blkoff + ws[warp] + (inc - tsum);
    int4 rp;
    rp.x = p; p += c0;
    rp.y = p; p += c1;
    rp.z = p; p += c2;
    rp.w = p;
    float4 dv;
    dv.x = rsqrtf((float)(c0 + 1));
    dv.y = rsqrtf((float)(c1 + 1));
    dv.z = rsqrtf((float)(c2 + 1));
    dv.w = rsqrtf((float)(c3 + 1));
    if (full) {
        *(int4*)(g_rowptr + base) = rp;
        *(int4*)(g_cursor + base) = rp;
        *(float4*)(g_dinv + base) = dv;
    } else {
        int rr[4] = {rp.x, rp.y, rp.z, rp.w};
        float dd[4] = {dv.x, dv.y, dv.z, dv.w};
        for (int k = 0; k < 4; k++)
            if (base + k < n) {
                g_rowptr[base + k] = rr[k];
                g_cursor[base + k] = rr[k];
                g_dinv[base + k] = dd[k];
            }
    }
}

__global__ void scatter_kernel(const int* __restrict__ src,
                               const int* __restrict__ dst, int E) {
    int e = blockIdx.x * blockDim.x + threadIdx.x;
    if (e < E) {
        int d = dst[e];
        int p = atomicAdd(&g_cursor[d], 1);
        g_colidx[p] = src[e];
    }
}

// ---------------- HMMA GEMM: g_tt_h = fp16( dinv ⊙ ( relu?(bn?(A)) @ W ) ) ----------------
// CTA tile 128x128, 8 warps (4M x 2N), warp tile m32 x n64, K=128.
// Split-bf16: A@W = Ah@Wh + Ah@Wl + Al@Wh, fp32 accumulators. (R7/R10 proven)
__device__ __forceinline__ void mma16816(float* d, const uint32_t* a,
                                         const uint32_t* b) {
    asm volatile(
        "mma.sync.aligned.m16n8k16.row.col.f32.bf16.bf16.f32 "
        "{%0,%1,%2,%3}, {%4,%5,%6,%7}, {%8,%9}, {%0,%1,%2,%3};"
        : "+f"(d[0]), "+f"(d[1]), "+f"(d[2]), "+f"(d[3])
        : "r"(a[0]), "r"(a[1]), "r"(a[2]), "r"(a[3]), "r"(b[0]), "r"(b[1]));
}

__device__ __forceinline__ uint32_t pack_bf16x2(float x, float y) {
    __nv_bfloat162 p;
    p.x = __float2bfloat16(x);
    p.y = __float2bfloat16(y);
    return *(uint32_t*)&p;
}

__global__ __launch_bounds__(256, 1)
void mma_gemm_kernel(const float* __restrict__ Ain, int layer, int n,
                     int applyBN) {
    extern __shared__ uint32_t smem[];
    uint32_t* sAh = smem;                       // 128 * ASTRIDE
    uint32_t* sAl = smem + 128 * ASTRIDE;
    uint32_t* sBh = smem + 2 * 128 * ASTRIDE;
    uint32_t* sBl = smem + 3 * 128 * ASTRIDE;
    int t = threadIdx.x;

    // ---- stage B: vectorized repack [n][k] -> smem stride ASTRIDE
    {
        const uint4* wh = (const uint4*)g_wt_hi[layer];
        const uint4* wl = (const uint4*)g_wt_lo[layer];
#pragma unroll
        for (int ii = 0; ii < 8; ii++) {
            int gidx = t + 256 * ii;       // uint4 index 0..2047
            int i = gidx * 4;              // word index
            int nn = i >> 6, q = i & 63;
            uint4 vh = wh[gidx];
            uint4 vl = wl[gidx];
            *(uint4*)&sBh[nn * ASTRIDE + q] = vh;
            *(uint4*)&sBl[nn * ASTRIDE + q] = vl;
        }
    }

    // ---- stage A: BN+ReLU then hi/lo bf16 split; 2 threads per row
    {
        const float* A = Ain ? Ain : g_agg;
        int r = t >> 1, half = t & 1;
        int grow = blockIdx.x * 128 + r;
        bool ok = (grow < n);
        const float* arow = A + (size_t)grow * 128 + half * 64;
        const float* scp = g_scale + half * 64;
        const float* shp = g_shift + half * 64;
        int wbase = r * ASTRIDE + half * 32;
#pragma unroll
        for (int i = 0; i < 16; i++) {
            float4 v = make_float4(0.f, 0.f, 0.f, 0.f);
            if (ok) v = *(const float4*)(arow + 4 * i);
            if (applyBN) {
                float4 sc = *(const float4*)(scp + 4 * i);
                float4 sh = *(const float4*)(shp + 4 * i);
                v.x = fmaxf(fmaf(v.x, sc.x, sh.x), 0.f);
                v.y = fmaxf(fmaf(v.y, sc.y, sh.y), 0.f);
                v.z = fmaxf(fmaf(v.z, sc.z, sh.z), 0.f);
                v.w = fmaxf(fmaf(v.w, sc.w, sh.w), 0.f);
            }
            uint2 hh, ll;
            hh.x = pack_bf16x2(v.x, v.y);
            hh.y = pack_bf16x2(v.z, v.w);
            float rx = v.x - __bfloat162float(__float2bfloat16(v.x));
            float ry = v.y - __bfloat162float(__float2bfloat16(v.y));
            float rz = v.z - __bfloat162float(__float2bfloat16(v.z));
            float rw = v.w - __bfloat162float(__float2bfloat16(v.w));
            ll.x = pack_bf16x2(rx, ry);
            ll.y = pack_bf16x2(rz, rw);
            *(uint2*)&sAh[wbase + 2 * i] = hh;
            *(uint2*)&sAl[wbase + 2 * i] = ll;
        }
    }
    __syncthreads();

    // ---- mainloop (pass-wise: proven fastest)
    int warp = t >> 5, lane = t & 31;
    int wm = (warp & 3) * 32;
    int wn = (warp >> 2) * 64;
    int qr = lane >> 2, qc = lane & 3;

    float acc[2][8][4];
#pragma unroll
    for (int mt = 0; mt < 2; mt++)
#pragma unroll
        for (int nt = 0; nt < 8; nt++)
#pragma unroll
            for (int j = 0; j < 4; j++) acc[mt][nt][j] = 0.f;

    const uint32_t* Aps[3] = { sAh, sAh, sAl };
    const uint32_t* Bps[3] = { sBh, sBl, sBh };

#pragma unroll
    for (int p = 0; p < 3; p++) {
        const uint32_t* a = Aps[p];
        const uint32_t* b = Bps[p];
#pragma unroll
        for (int ks = 0; ks < 8; ks++) {
            uint32_t af[2][4];
#pragma unroll
            for (int mt = 0; mt < 2; mt++) {
                int base = (wm + mt * 16 + qr) * ASTRIDE + ks * 8 + qc;
                af[mt][0] = a[base];
                af[mt][1] = a[base + 8 * ASTRIDE];
                af[mt][2] = a[base + 4];
                af[mt][3] = a[base + 8 * ASTRIDE + 4];
            }
            uint32_t bf[8][2];
#pragma unroll
            for (int nt = 0; nt < 8; nt++) {
                int nb = (wn + nt * 8 + qr) * ASTRIDE + ks * 8 + qc;
                bf[nt][0] = b[nb];
                bf[nt][1] = b[nb + 4];
            }
#pragma unroll
            for (int mt = 0; mt < 2; mt++)
#pragma unroll
                for (int nt = 0; nt < 8; nt++)
                    mma16816(acc[mt][nt], af[mt], bf[nt]);
        }
    }

    // ---- epilogue: scale by dinv[row], convert fp16, store to g_tt_h
#pragma unroll
    for (int mt = 0; mt < 2; mt++) {
        int r0 = blockIdx.x * 128 + wm + mt * 16 + qr;
        int r1 = r0 + 8;
        bool ok0 = (r0 < n), ok1 = (r1 < n);
        float dv0 = ok0 ? g_dinv[r0] : 0.f;
        float dv1 = ok1 ? g_dinv[r1] : 0.f;
        __half* p0 = g_tt_h + (size_t)r0 * 128 + wn + qc * 2;
        __half* p1 = g_tt_h + (size_t)r1 * 128 + wn + qc * 2;
#pragma unroll
        for (int nt = 0; nt < 8; nt++) {
            if (ok0)
                *(__half2*)(p0 + nt * 8) =
                    __floats2half2_rn(acc[mt][nt][0] * dv0, acc[mt][nt][1] * dv0);
            if (ok1)
                *(__half2*)(p1 + nt * 8) =
                    __floats2half2_rn(acc[mt][nt][2] * dv1, acc[mt][nt][3] * dv1);
        }
    }
}

// ---------------- SpMM gather (fp16 rows, fp32 accum, MLP=8) + fused stats ----------------
__device__ __forceinline__ void acc_u2(float4& a, uint2 u) {
    float2 f0 = __half22float2(*(__half2*)&u.x);
    float2 f1 = __half22float2(*(__half2*)&u.y);
    a.x += f0.x; a.y += f0.y; a.z += f1.x; a.w += f1.y;
}

__global__ __launch_bounds__(256)
void spmm_kernel(const float* __restrict__ bias, int n) {
    __shared__ float s_ps[8][128];
    __shared__ float s_pq[8][128];
    int warp = threadIdx.x >> 5;
    int lane = threadIdx.x & 31;
    int gw = (blockIdx.x << 3) + warp;
    int nwarps = gridDim.x << 3;
    int c = lane * 4;
    float4 b4 = *(const float4*)(bias + c);

    float4 ps = make_float4(0.f, 0.f, 0.f, 0.f);
    float4 pq = make_float4(0.f, 0.f, 0.f, 0.f);

    for (int i = gw; i < n; i += nwarps) {
        int s = g_rowptr[i], e = g_rowptr[i + 1];
        float4 acc = make_float4(0.f, 0.f, 0.f, 0.f);
        float4 acc2 = make_float4(0.f, 0.f, 0.f, 0.f);
        {   // self loop
            uint2 u = *(const uint2*)(g_tt_h + (size_t)i * D + c);
            acc_u2(acc, u);
        }
        for (int base = s; base < e; base += 32) {
            int rem = e - base;
            int m = rem < 32 ? rem : 32;
            int idx = 0;
            if (base + lane < e) idx = g_colidx[base + lane];
            int j = 0;
            for (; j + 8 <= m; j += 8) {
                int s0 = __shfl_sync(0xffffffffu, idx, j);
                int s1 = __shfl_sync(0xffffffffu, idx, j + 1);
                int s2 = __shfl_sync(0xffffffffu, idx, j + 2);
                int s3 = __shfl_sync(0xffffffffu, idx, j + 3);
                int s4 = __shfl_sync(0xffffffffu, idx, j + 4);
                int s5 = __shfl_sync(0xffffffffu, idx, j + 5);
                int s6 = __shfl_sync(0xffffffffu, idx, j + 6);
                int s7 = __shfl_sync(0xffffffffu, idx, j + 7);
                uint2 u0 = *(const uint2*)(g_tt_h + (size_t)s0 * D + c);
                uint2 u1 = *(const uint2*)(g_tt_h + (size_t)s1 * D + c);
                uint2 u2 = *(const uint2*)(g_tt_h + (size_t)s2 * D + c);
                uint2 u3 = *(const uint2*)(g_tt_h + (size_t)s3 * D + c);
                uint2 u4 = *(const uint2*)(g_tt_h + (size_t)s4 * D + c);
                uint2 u5 = *(const uint2*)(g_tt_h + (size_t)s5 * D + c);
                uint2 u6 = *(const uint2*)(g_tt_h + (size_t)s6 * D + c);
                uint2 u7 = *(const uint2*)(g_tt_h + (size_t)s7 * D + c);
                acc_u2(acc, u0);  acc_u2(acc2, u1);
                acc_u2(acc, u2);  acc_u2(acc2, u3);
                acc_u2(acc, u4);  acc_u2(acc2, u5);
                acc_u2(acc, u6);  acc_u2(acc2, u7);
            }
            for (; j + 4 <= m; j += 4) {
                int s0 = __shfl_sync(0xffffffffu, idx, j);
                int s1 = __shfl_sync(0xffffffffu, idx, j + 1);
                int s2 = __shfl_sync(0xffffffffu, idx, j + 2);
                int s3 = __shfl_sync(0xffffffffu, idx, j + 3);
                uint2 u0 = *(const uint2*)(g_tt_h + (size_t)s0 * D + c);
                uint2 u1 = *(const uint2*)(g_tt_h + (size_t)s1 * D + c);
                uint2 u2 = *(const uint2*)(g_tt_h + (size_t)s2 * D + c);
                uint2 u3 = *(const uint2*)(g_tt_h + (size_t)s3 * D + c);
                acc_u2(acc, u0);  acc_u2(acc2, u1);
                acc_u2(acc, u2);  acc_u2(acc2, u3);
            }
            for (; j < m; j++) {
                int s0 = __shfl_sync(0xffffffffu, idx, j);
                uint2 u = *(const uint2*)(g_tt_h + (size_t)s0 * D + c);
                acc_u2(acc, u);
            }
        }
        acc.x += acc2.x; acc.y += acc2.y; acc.z += acc2.z; acc.w += acc2.w;
        float dv = g_dinv[i];
        float4 o;
        o.x = fmaf(acc.x, dv, b4.x);
        o.y = fmaf(acc.y, dv, b4.y);
        o.z = fmaf(acc.z, dv, b4.z);
        o.w = fmaf(acc.w, dv, b4.w);
        *(float4*)(g_agg + (size_t)i * D + c) = o;
        ps.x += o.x; ps.y += o.y; ps.z += o.z; ps.w += o.w;
        pq.x = fmaf(o.x, o.x, pq.x);
        pq.y = fmaf(o.y, o.y, pq.y);
        pq.z = fmaf(o.z, o.z, pq.z);
        pq.w = fmaf(o.w, o.w, pq.w);
    }

    *(float4*)&s_ps[warp][c] = ps;
    *(float4*)&s_pq[warp][c] = pq;
    __syncthreads();

    int t = threadIdx.x;
    int col = t & 127;
    bool doSq = (t >= 128);
    float a = 0.f;
#pragma unroll
    for (int w = 0; w < 8; w++)
        a += doSq ? s_pq[w][col] : s_ps[w][col];
    if (doSq) g_psq[blockIdx.x * D + col] = a;
    else      g_psum[blockIdx.x * D + col] = a;
}

// ---------------- BN finalize: one block per column; optional pool zero ----------------
__global__ __launch_bounds__(256)
void bnfinal_kernel(const float* __restrict__ gamma,
                    const float* __restrict__ beta, int n, int nb,
                    float* __restrict__ pool, int G, int zeroPool) {
    int c = blockIdx.x;          // 0..127
    int t = threadIdx.x;         // 256
    float s = 0.f, q = 0.f;
    for (int b = t; b < nb; b += 256) {
        s += g_psum[b * D + c];
        q += g_psq[b * D + c];
    }
    __shared__ float rs[256], rq[256];
    rs[t] = s; rq[t] = q;
    __syncthreads();
    for (int off = 128; off > 0; off >>= 1) {
        if (t < off) { rs[t] += rs[t + off]; rq[t] += rq[t + off]; }
        __syncthreads();
    }
    if (t == 0) {
        float inv_n = 1.0f / (float)n;
        float mu = rs[0] * inv_n;
        float var = fmaxf(rq[0] * inv_n - mu * mu, 0.f);
        float rsq = rsqrtf(var + 1e-5f);
        float sc = gamma[c] * rsq;
        g_scale[c] = sc;
        g_shift[c] = fmaf(-mu, sc, beta[c]);
    }
    if (zeroPool) {
        for (int g = t; g < G; g += 256)
            pool[(size_t)g * D + c] = 0.f;
    }
}

// ---------------- final BN+ReLU -> h out, pooled sum -> pool out ----------------
__global__ void finalize_kernel(const int* __restrict__ batch,
                                float* __restrict__ hout,
                                float* __restrict__ pool, int n) {
    int gw = (blockIdx.x * blockDim.x + threadIdx.x) >> 5;
    int lane = threadIdx.x & 31;
    int nch = (n + 15) >> 4;
    if (gw >= nch) return;
    int r0 = gw << 4;
    int r1 = r0 + 16; if (r1 > n) r1 = n;
    int c = lane * 4;
    float4 sc = *(const float4*)(g_scale + c);
    float4 sh = *(const float4*)(g_shift + c);

    float4 acc = make_float4(0.f, 0.f, 0.f, 0.f);
    int gprev = -1;
    for (int r = r0; r < r1; r++) {
        float4 v = *(const float4*)(g_agg + (size_t)r * D + c);
        float4 h;
        h.x = fmaxf(fmaf(v.x, sc.x, sh.x), 0.f);
        h.y = fmaxf(fmaf(v.y, sc.y, sh.y), 0.f);
        h.z = fmaxf(fmaf(v.z, sc.z, sh.z), 0.f);
        h.w = fmaxf(fmaf(v.w, sc.w, sh.w), 0.f);
        *(float4*)(hout + (size_t)r * D + c) = h;
        int g = batch[r];
        if (g != gprev) {
            if (gprev >= 0) {
                float* p = pool + (size_t)gprev * D + c;
                atomicAdd(p + 0, acc.x); atomicAdd(p + 1, acc.y);
                atomicAdd(p + 2, acc.z); atomicAdd(p + 3, acc.w);
            }
            acc = make_float4(0.f, 0.f, 0.f, 0.f);
            gprev = g;
        }
        acc.x += h.x; acc.y += h.y; acc.z += h.z; acc.w += h.w;
    }
    if (gprev >= 0) {
        float* p = pool + (size_t)gprev * D + c;
        atomicAdd(p + 0, acc.x); atomicAdd(p + 1, acc.y);
        atomicAdd(p + 2, acc.z); atomicAdd(p + 3, acc.w);
    }
}

// ---------------- launch ----------------
extern "C" void kernel_launch(void* const* d_in, const int* in_sizes, int n_in,
                              void* d_out, int out_size) {
    const float* x      = (const float*)d_in[0];
    const int*   ei     = (const int*)d_in[1];
    const int*   batch  = (const int*)d_in[2];
    const float* Ws     = (const float*)d_in[3];
    const float* bs     = (const float*)d_in[4];
    const float* gammas = (const float*)d_in[5];
    const float* betas  = (const float*)d_in[6];

    int n = in_sizes[2];
    int E = in_sizes[1] / 2;
    int L = in_sizes[3] / (D * D);
    int G = out_size / D - n;

    const int* src = ei;
    const int* dst = ei + E;
    float* hout = (float*)d_out;
    float* pool = hout + (size_t)n * D;

    const int tb = 256;
    int nblk = (n + SCAN_ELEMS - 1) / SCAN_ELEMS;

    const int DYN_SMEM = 4 * 128 * ASTRIDE * 4;   // 139264 bytes
    cudaFuncSetAttribute(mma_gemm_kernel,
                         cudaFuncAttributeMaxDynamicSharedMemorySize, DYN_SMEM);

    // Graph preprocessing (5 launches)
    int prepN = n > L * 16384 ? n : L * 16384;
    prep_kernel<<<(prepN + tb - 1) / tb, tb>>>(Ws, L, n);
    count_kernel<<<(E + tb - 1) / tb, tb>>>(dst, E);
    scan_reduce_kernel<<<nblk, 1024>>>(n);
    scan_write_kernel<<<nblk, 1024>>>(n, nblk);
    scatter_kernel<<<(E + tb - 1) / tb, tb>>>(src, dst, E);

    int gblocks = (n + 127) / 128;
    for (int l = 0; l < L; l++) {
        mma_gemm_kernel<<<gblocks, 256, DYN_SMEM>>>(l == 0 ? x : nullptr,
                                                    l, n, l > 0 ? 1 : 0);
        spmm_kernel<<<NSB, 256>>>(bs + (size_t)l * D, n);
        bnfinal_kernel<<<D, 256>>>(gammas + (size_t)l * D, betas + (size_t)l * D,
                                   n, NSB, pool, G, (l == L - 1) ? 1 : 0);
    }

    int nch = (n + 15) / 16;
    finalize_kernel<<<(nch * 32 + tb - 1) / tb, tb>>>(batch, hout, pool, n);
}